// round 1
// baseline (speedup 1.0000x reference)
#include <cuda_runtime.h>
#include <math.h>

#define BB 64
#define NN 256
#define HH 8
#define FF 256
#define D_GAT 2048
#define D_LBL 512
#define D_VIS 2048
#define D_EMB 512
#define ALPHA 0.2f

// ---------------- scratch (device globals; no allocations allowed) ----------
__device__ float g_L[NN * D_GAT];                      // labels @ W_lbl     (2 MiB)
__device__ float g_V[BB * D_GAT];                      // visual @ W_vis     (0.5 MiB)
__device__ float g_Ls[NN * HH];
__device__ float g_Ld[NN * HH];
__device__ float g_Vs[BB * HH];
__device__ float g_Vd[BB * HH];
__device__ float g_attn[(size_t)BB * HH * NN * NN];    // 128 MiB
__device__ float g_out[(size_t)BB * NN * D_GAT];       // 128 MiB (post-ELU)
__device__ float g_logits[BB * NN];
__device__ float g_pw[BB * NN];
__device__ float g_pooled[BB * D_GAT];

// ---------------- helpers ---------------------------------------------------
__device__ __forceinline__ float warp_sum(float v) {
    #pragma unroll
    for (int o = 16; o; o >>= 1) v += __shfl_xor_sync(0xffffffffu, v, o);
    return v;
}
__device__ __forceinline__ float warp_max(float v) {
    #pragma unroll
    for (int o = 16; o; o >>= 1) v = fmaxf(v, __shfl_xor_sync(0xffffffffu, v, o));
    return v;
}

// ---------------- generic fp32 tiled GEMM: C = A(MxK) * B(KxN) [+bias] ------
// 64x64 tile, BK=16, 256 threads, 4x4 per thread. M,N mult of 64 (M>=64), K mult of 16.
__global__ void gemm_f32(const float* __restrict__ A, int lda,
                         const float* __restrict__ Bm, int ldb,
                         float* __restrict__ C, int ldc,
                         int K, const float* __restrict__ bias)
{
    __shared__ float As[16][64];
    __shared__ float Bs[16][64];
    const int tid = threadIdx.x;
    const int tx = tid & 15, ty = tid >> 4;
    const int colBase = blockIdx.x * 64;
    const int rowBase = blockIdx.y * 64;

    const int am = tid >> 2;          // 0..63
    const int ak = (tid & 3) * 4;     // 0,4,8,12
    const int bk = tid >> 4;          // 0..15
    const int bn = (tid & 15) * 4;    // 0..60

    float acc[4][4] = {};

    for (int k0 = 0; k0 < K; k0 += 16) {
        float4 av = *(const float4*)&A[(size_t)(rowBase + am) * lda + k0 + ak];
        As[ak + 0][am] = av.x; As[ak + 1][am] = av.y;
        As[ak + 2][am] = av.z; As[ak + 3][am] = av.w;
        *(float4*)&Bs[bk][bn] =
            *(const float4*)&Bm[(size_t)(k0 + bk) * ldb + colBase + bn];
        __syncthreads();
        #pragma unroll
        for (int kk = 0; kk < 16; kk++) {
            float ra[4], rb[4];
            #pragma unroll
            for (int i = 0; i < 4; i++) ra[i] = As[kk][ty * 4 + i];
            #pragma unroll
            for (int j = 0; j < 4; j++) rb[j] = Bs[kk][tx * 4 + j];
            #pragma unroll
            for (int i = 0; i < 4; i++)
                #pragma unroll
                for (int j = 0; j < 4; j++)
                    acc[i][j] += ra[i] * rb[j];
        }
        __syncthreads();
    }
    #pragma unroll
    for (int i = 0; i < 4; i++) {
        int r = rowBase + ty * 4 + i;
        #pragma unroll
        for (int j = 0; j < 4; j++) {
            int cc = colBase + tx * 4 + j;
            float v = acc[i][j];
            if (bias) v += bias[cc];
            C[(size_t)r * ldc + cc] = v;
        }
    }
}

// ---------------- per-node / per-sample attention scalars -------------------
// blocks [0, N*H): Ls/Ld from g_L ; blocks [N*H, N*H+B*H): Vs/Vd from g_V
__global__ void dots_kernel(const float* __restrict__ a_src,
                            const float* __restrict__ a_dst)
{
    __shared__ float ss[8], sd[8];
    int idx = blockIdx.x, t = threadIdx.x;
    const float* vec; float *outS, *outD; int h;
    if (idx < NN * HH) {
        int n = idx >> 3; h = idx & 7;
        vec = &g_L[(size_t)n * D_GAT + h * FF];
        outS = &g_Ls[idx]; outD = &g_Ld[idx];
    } else {
        int k = idx - NN * HH;
        int b = k >> 3; h = k & 7;
        vec = &g_V[(size_t)b * D_GAT + h * FF];
        outS = &g_Vs[k]; outD = &g_Vd[k];
    }
    float v = vec[t];
    float s = warp_sum(v * a_src[h * FF + t]);
    float d = warp_sum(v * a_dst[h * FF + t]);
    int w = t >> 5, l = t & 31;
    if (l == 0) { ss[w] = s; sd[w] = d; }
    __syncthreads();
    if (t == 0) {
        float S = 0.f, D = 0.f;
        #pragma unroll
        for (int i = 0; i < 8; i++) { S += ss[i]; D += sd[i]; }
        *outS = S; *outD = D;
    }
}

// ---------------- masked LeakyReLU softmax rows -----------------------------
// one warp per (b,h,i) row; 8 warps per block
__global__ void attn_softmax_kernel(const float* __restrict__ adj)
{
    int warp = threadIdx.x >> 5, lane = threadIdx.x & 31;
    int row = blockIdx.x * 8 + warp;           // 0 .. B*H*N-1
    int i = row & (NN - 1);
    int bh = row >> 8;
    int h = bh & 7, b = bh >> 3;
    float c = g_Ls[i * HH + h] + g_Vs[b * HH + h] + g_Vd[b * HH + h];

    float vals[8];
    float m = -3.4e38f;
    #pragma unroll
    for (int t = 0; t < 8; t++) {
        int j = lane + t * 32;
        float a = adj[i * NN + j];
        float e = c + g_Ld[j * HH + h];
        e = e > 0.f ? e : ALPHA * e;
        vals[t] = (a > 0.f) ? e : -3.4e38f;
        m = fmaxf(m, vals[t]);
    }
    m = warp_max(m);
    float s = 0.f;
    #pragma unroll
    for (int t = 0; t < 8; t++) {
        vals[t] = (vals[t] > -1e38f) ? __expf(vals[t] - m) : 0.f;
        s += vals[t];
    }
    s = warp_sum(s);
    float inv = 1.f / s;
    float* dst = &g_attn[(size_t)row * NN];
    #pragma unroll
    for (int t = 0; t < 8; t++) dst[lane + t * 32] = vals[t] * inv;
}

// ---------------- batched attn @ L_h  (+V, ELU) -----------------------------
// grid (4,4,B*H); 64x64 tile, K=256
__global__ void attn_gemm_kernel()
{
    __shared__ float As[16][64];
    __shared__ float Bs[16][64];
    const int z = blockIdx.z;
    const int b = z >> 3, h = z & 7;
    const float* A  = &g_attn[(size_t)z * NN * NN];          // lda = 256
    const float* Bm = &g_L[h * FF];                          // ldb = 2048
    const float* bias = &g_V[(size_t)b * D_GAT + h * FF];
    float* C = &g_out[(size_t)b * NN * D_GAT + h * FF];      // ldc = 2048

    const int tid = threadIdx.x;
    const int tx = tid & 15, ty = tid >> 4;
    const int colBase = blockIdx.x * 64;
    const int rowBase = blockIdx.y * 64;
    const int am = tid >> 2;
    const int ak = (tid & 3) * 4;
    const int bk = tid >> 4;
    const int bn = (tid & 15) * 4;

    float acc[4][4] = {};
    for (int k0 = 0; k0 < NN; k0 += 16) {
        float4 av = *(const float4*)&A[(size_t)(rowBase + am) * NN + k0 + ak];
        As[ak + 0][am] = av.x; As[ak + 1][am] = av.y;
        As[ak + 2][am] = av.z; As[ak + 3][am] = av.w;
        *(float4*)&Bs[bk][bn] =
            *(const float4*)&Bm[(size_t)(k0 + bk) * D_GAT + colBase + bn];
        __syncthreads();
        #pragma unroll
        for (int kk = 0; kk < 16; kk++) {
            float ra[4], rb[4];
            #pragma unroll
            for (int i = 0; i < 4; i++) ra[i] = As[kk][ty * 4 + i];
            #pragma unroll
            for (int j = 0; j < 4; j++) rb[j] = Bs[kk][tx * 4 + j];
            #pragma unroll
            for (int i = 0; i < 4; i++)
                #pragma unroll
                for (int j = 0; j < 4; j++)
                    acc[i][j] += ra[i] * rb[j];
        }
        __syncthreads();
    }
    #pragma unroll
    for (int i = 0; i < 4; i++) {
        int r = rowBase + ty * 4 + i;
        #pragma unroll
        for (int j = 0; j < 4; j++) {
            int cc = colBase + tx * 4 + j;
            float v = acc[i][j] + bias[cc];
            v = v > 0.f ? v : expm1f(v);     // ELU
            C[(size_t)r * D_GAT + cc] = v;
        }
    }
}

// ---------------- pooling logits: out . pool_q ------------------------------
__global__ void logits_kernel(const float* __restrict__ pool_q)
{
    __shared__ float sh[8];
    int bn = blockIdx.x, t = threadIdx.x;
    const float* row = &g_out[(size_t)bn * D_GAT];
    float s = 0.f;
    #pragma unroll
    for (int k = 0; k < 8; k++) {
        int d = t + k * 256;
        s += row[d] * pool_q[d];
    }
    s = warp_sum(s);
    if ((t & 31) == 0) sh[t >> 5] = s;
    __syncthreads();
    if (t == 0) {
        float S = 0.f;
        #pragma unroll
        for (int i = 0; i < 8; i++) S += sh[i];
        g_logits[bn] = S;
    }
}

// ---------------- softmax over the N label nodes ----------------------------
__global__ void pw_kernel()
{
    __shared__ float sh[8];
    __shared__ float bc;
    int b = blockIdx.x, t = threadIdx.x;
    float x = g_logits[b * NN + t];
    float m = warp_max(x);
    if ((t & 31) == 0) sh[t >> 5] = m;
    __syncthreads();
    if (t < 8) {
        float v = sh[t];
        #pragma unroll
        for (int o = 4; o; o >>= 1) v = fmaxf(v, __shfl_xor_sync(0xffu, v, o));
        if (t == 0) bc = v;
    }
    __syncthreads();
    float M = bc;
    float e = __expf(x - M);
    float s = warp_sum(e);
    if ((t & 31) == 0) sh[t >> 5] = s;
    __syncthreads();
    if (t < 8) {
        float v = sh[t];
        #pragma unroll
        for (int o = 4; o; o >>= 1) v += __shfl_xor_sync(0xffu, v, o);
        if (t == 0) bc = v;
    }
    __syncthreads();
    g_pw[b * NN + t] = e / bc;
}

// ---------------- pooled[b,d] = sum_n pw[b,n] * out[b,n,d] ------------------
// grid (8, 64): x = 256-col chunk of d, y = b
__global__ void pooled_kernel()
{
    __shared__ float pw_s[NN];
    int b = blockIdx.y;
    int d = blockIdx.x * 256 + threadIdx.x;
    pw_s[threadIdx.x] = g_pw[b * NN + threadIdx.x];
    __syncthreads();
    const float* base = &g_out[(size_t)b * NN * D_GAT + d];
    float acc = 0.f;
    #pragma unroll 4
    for (int n = 0; n < NN; n++) acc += pw_s[n] * base[(size_t)n * D_GAT];
    g_pooled[b * D_GAT + d] = acc;
}

// ---------------- launch ----------------------------------------------------
extern "C" void kernel_launch(void* const* d_in, const int* in_sizes, int n_in,
                              void* d_out, int out_size)
{
    const float* visual = (const float*)d_in[0];   // (64, 2048)
    const float* labels = (const float*)d_in[1];   // (256, 512)
    const float* adj    = (const float*)d_in[2];   // (256, 256)
    const float* W      = (const float*)d_in[3];   // (2560, 8, 256)
    const float* a_src  = (const float*)d_in[4];   // (8, 256)
    const float* a_dst  = (const float*)d_in[5];   // (8, 256)
    const float* pool_q = (const float*)d_in[6];   // (2048,)
    const float* fcW    = (const float*)d_in[7];   // (2048, 512)
    const float* fcb    = (const float*)d_in[8];   // (512,)
    float* out = (float*)d_out;                    // (64, 512)

    float *pL, *pV, *pPooled;
    cudaGetSymbolAddress((void**)&pL, g_L);
    cudaGetSymbolAddress((void**)&pV, g_V);
    cudaGetSymbolAddress((void**)&pPooled, g_pooled);

    // L = labels @ W[:512]       (256 x 2048, K=512)
    gemm_f32<<<dim3(D_GAT / 64, NN / 64), 256>>>(
        labels, D_LBL, W, D_GAT, pL, D_GAT, D_LBL, nullptr);
    // V = visual @ W[512:]       (64 x 2048, K=2048)
    gemm_f32<<<dim3(D_GAT / 64, BB / 64), 256>>>(
        visual, D_VIS, W + (size_t)D_LBL * D_GAT, D_GAT, pV, D_GAT, D_VIS, nullptr);
    // per-node/per-sample attention scalars
    dots_kernel<<<NN * HH + BB * HH, 256>>>(a_src, a_dst);
    // masked softmax rows
    attn_softmax_kernel<<<(BB * HH * NN) / 8, 256>>>(adj);
    // out = ELU(attn @ L_h + V)
    attn_gemm_kernel<<<dim3(NN / 64, NN / 64, BB * HH), 256>>>();
    // attention pooling
    logits_kernel<<<BB * NN, 256>>>(pool_q);
    pw_kernel<<<BB, 256>>>();
    pooled_kernel<<<dim3(D_GAT / 256, BB), 256>>>();
    // final fc
    gemm_f32<<<dim3(D_EMB / 64, BB / 64), 256>>>(
        pPooled, D_GAT, fcW, D_EMB, out, D_EMB, D_VIS, fcb);
}

// round 2
// speedup vs baseline: 1.4125x; 1.4125x over previous
#include <cuda_runtime.h>
#include <math.h>

#define BB 64
#define NN 256
#define HH 8
#define FF 256
#define D_GAT 2048
#define D_LBL 512
#define D_VIS 2048
#define D_EMB 512
#define ALPHA 0.2f

// ---------------- scratch (device globals; no allocations allowed) ----------
__device__ float g_L[NN * D_GAT];                      // labels @ W_lbl     (2 MiB)
__device__ float g_V[BB * D_GAT];                      // visual @ W_vis     (0.5 MiB)
__device__ float g_Vpart[8 * BB * D_GAT];              // split-K partials   (4 MiB)
__device__ float g_fcpart[4 * BB * D_EMB];             // split-K partials
__device__ float g_Ls[NN * HH];
__device__ float g_Ld[NN * HH];
__device__ float g_Vs[BB * HH];
__device__ float g_Vd[BB * HH];
__device__ float g_attn[(size_t)BB * HH * NN * NN];    // 128 MiB
__device__ float g_out[(size_t)BB * NN * D_GAT];       // 128 MiB (post-ELU)
__device__ float g_logits[BB * NN];
__device__ float g_pw[BB * NN];
__device__ float g_pooled[BB * D_GAT];

// ---------------- helpers ---------------------------------------------------
__device__ __forceinline__ float warp_sum(float v) {
    #pragma unroll
    for (int o = 16; o; o >>= 1) v += __shfl_xor_sync(0xffffffffu, v, o);
    return v;
}
__device__ __forceinline__ float warp_max(float v) {
    #pragma unroll
    for (int o = 16; o; o >>= 1) v = fmaxf(v, __shfl_xor_sync(0xffffffffu, v, o));
    return v;
}
// packed f32x2 FMA (SASS FFMA2) — only reachable via PTX
__device__ __forceinline__ void ffma2(unsigned long long& acc,
                                      unsigned long long a,
                                      unsigned long long b) {
    asm("fma.rn.f32x2 %0, %1, %2, %0;" : "+l"(acc) : "l"(a), "l"(b));
}
__device__ __forceinline__ unsigned long long pack2(float x) {
    unsigned long long r;
    asm("mov.b64 %0, {%1, %1};" : "=l"(r) : "r"(__float_as_uint(x)));
    return r;
}
__device__ __forceinline__ void unpack2(unsigned long long p, float& lo, float& hi) {
    unsigned int a, b;
    asm("mov.b64 {%0, %1}, %2;" : "=r"(a), "=r"(b) : "l"(p));
    lo = __uint_as_float(a); hi = __uint_as_float(b);
}

// ---------------- generic fp32 tiled GEMM: C = A(MxK) * B(KxN) --------------
// 64x64 tile, BK=16, 256 threads, 4x4 per thread.
__global__ void gemm_f32(const float* __restrict__ A, int lda,
                         const float* __restrict__ Bm, int ldb,
                         float* __restrict__ C, int ldc, int K)
{
    __shared__ float As[16][64];
    __shared__ float Bs[16][64];
    const int tid = threadIdx.x;
    const int tx = tid & 15, ty = tid >> 4;
    const int colBase = blockIdx.x * 64;
    const int rowBase = blockIdx.y * 64;
    const int am = tid >> 2;
    const int ak = (tid & 3) * 4;
    const int bk = tid >> 4;
    const int bn = (tid & 15) * 4;
    float acc[4][4] = {};
    for (int k0 = 0; k0 < K; k0 += 16) {
        float4 av = *(const float4*)&A[(size_t)(rowBase + am) * lda + k0 + ak];
        As[ak + 0][am] = av.x; As[ak + 1][am] = av.y;
        As[ak + 2][am] = av.z; As[ak + 3][am] = av.w;
        *(float4*)&Bs[bk][bn] =
            *(const float4*)&Bm[(size_t)(k0 + bk) * ldb + colBase + bn];
        __syncthreads();
        #pragma unroll
        for (int kk = 0; kk < 16; kk++) {
            float ra[4], rb[4];
            #pragma unroll
            for (int i = 0; i < 4; i++) ra[i] = As[kk][ty * 4 + i];
            #pragma unroll
            for (int j = 0; j < 4; j++) rb[j] = Bs[kk][tx * 4 + j];
            #pragma unroll
            for (int i = 0; i < 4; i++)
                #pragma unroll
                for (int j = 0; j < 4; j++)
                    acc[i][j] += ra[i] * rb[j];
        }
        __syncthreads();
    }
    #pragma unroll
    for (int i = 0; i < 4; i++) {
        int r = rowBase + ty * 4 + i;
        #pragma unroll
        for (int j = 0; j < 4; j++)
            C[(size_t)r * ldc + colBase + tx * 4 + j] = acc[i][j];
    }
}

// split-K variant: blockIdx.z selects K-chunk; writes partials
__global__ void gemm_f32_splitk(const float* __restrict__ A, int lda,
                                const float* __restrict__ Bm, int ldb,
                                float* __restrict__ Cpart, int ldc,
                                int kChunk, size_t partStride)
{
    __shared__ float As[16][64];
    __shared__ float Bs[16][64];
    const int tid = threadIdx.x;
    const int tx = tid & 15, ty = tid >> 4;
    const int colBase = blockIdx.x * 64;
    const int rowBase = blockIdx.y * 64;
    const int kBase = blockIdx.z * kChunk;
    const int am = tid >> 2;
    const int ak = (tid & 3) * 4;
    const int bk = tid >> 4;
    const int bn = (tid & 15) * 4;
    float acc[4][4] = {};
    for (int k0 = kBase; k0 < kBase + kChunk; k0 += 16) {
        float4 av = *(const float4*)&A[(size_t)(rowBase + am) * lda + k0 + ak];
        As[ak + 0][am] = av.x; As[ak + 1][am] = av.y;
        As[ak + 2][am] = av.z; As[ak + 3][am] = av.w;
        *(float4*)&Bs[bk][bn] =
            *(const float4*)&Bm[(size_t)(k0 + bk) * ldb + colBase + bn];
        __syncthreads();
        #pragma unroll
        for (int kk = 0; kk < 16; kk++) {
            float ra[4], rb[4];
            #pragma unroll
            for (int i = 0; i < 4; i++) ra[i] = As[kk][ty * 4 + i];
            #pragma unroll
            for (int j = 0; j < 4; j++) rb[j] = Bs[kk][tx * 4 + j];
            #pragma unroll
            for (int i = 0; i < 4; i++)
                #pragma unroll
                for (int j = 0; j < 4; j++)
                    acc[i][j] += ra[i] * rb[j];
        }
        __syncthreads();
    }
    float* C = Cpart + blockIdx.z * partStride;
    #pragma unroll
    for (int i = 0; i < 4; i++) {
        int r = rowBase + ty * 4 + i;
        #pragma unroll
        for (int j = 0; j < 4; j++)
            C[(size_t)r * ldc + colBase + tx * 4 + j] = acc[i][j];
    }
}

// sum nparts partial matrices; optional bias (period = mask+1, pow2)
__global__ void reduce_parts(const float* __restrict__ part,
                             float* __restrict__ outp,
                             int nparts, size_t stride, int total,
                             const float* __restrict__ bias, int mask)
{
    int i = blockIdx.x * 256 + threadIdx.x;
    if (i >= total) return;
    float s = 0.f;
    for (int p = 0; p < nparts; p++) s += part[p * stride + i];
    if (bias) s += bias[i & mask];
    outp[i] = s;
}

// ---------------- per-node / per-sample attention scalars -------------------
__global__ void dots_kernel(const float* __restrict__ a_src,
                            const float* __restrict__ a_dst)
{
    __shared__ float ss[8], sd[8];
    int idx = blockIdx.x, t = threadIdx.x;
    const float* vec; float *outS, *outD; int h;
    if (idx < NN * HH) {
        int n = idx >> 3; h = idx & 7;
        vec = &g_L[(size_t)n * D_GAT + h * FF];
        outS = &g_Ls[idx]; outD = &g_Ld[idx];
    } else {
        int k = idx - NN * HH;
        int b = k >> 3; h = k & 7;
        vec = &g_V[(size_t)b * D_GAT + h * FF];
        outS = &g_Vs[k]; outD = &g_Vd[k];
    }
    float v = vec[t];
    float s = warp_sum(v * a_src[h * FF + t]);
    float d = warp_sum(v * a_dst[h * FF + t]);
    int w = t >> 5, l = t & 31;
    if (l == 0) { ss[w] = s; sd[w] = d; }
    __syncthreads();
    if (t == 0) {
        float S = 0.f, D = 0.f;
        #pragma unroll
        for (int i = 0; i < 8; i++) { S += ss[i]; D += sd[i]; }
        *outS = S; *outD = D;
    }
}

// ---------------- masked LeakyReLU softmax rows -----------------------------
__global__ void attn_softmax_kernel(const float* __restrict__ adj)
{
    int warp = threadIdx.x >> 5, lane = threadIdx.x & 31;
    int row = blockIdx.x * 8 + warp;
    int i = row & (NN - 1);
    int bh = row >> 8;
    int h = bh & 7, b = bh >> 3;
    float c = g_Ls[i * HH + h] + g_Vs[b * HH + h] + g_Vd[b * HH + h];
    float vals[8];
    float m = -3.4e38f;
    #pragma unroll
    for (int t = 0; t < 8; t++) {
        int j = lane + t * 32;
        float a = adj[i * NN + j];
        float e = c + g_Ld[j * HH + h];
        e = e > 0.f ? e : ALPHA * e;
        vals[t] = (a > 0.f) ? e : -3.4e38f;
        m = fmaxf(m, vals[t]);
    }
    m = warp_max(m);
    float s = 0.f;
    #pragma unroll
    for (int t = 0; t < 8; t++) {
        vals[t] = (vals[t] > -1e38f) ? __expf(vals[t] - m) : 0.f;
        s += vals[t];
    }
    s = warp_sum(s);
    float inv = 1.f / s;
    float* dst = &g_attn[(size_t)row * NN];
    #pragma unroll
    for (int t = 0; t < 8; t++) dst[lane + t * 32] = vals[t] * inv;
}

// ---------------- batched attn @ L_h (+V, ELU) with packed FFMA2 ------------
// 128x128 tile, BK=16, 256 threads, 8x8 microtile, grid (2,2,512)
__global__ void __launch_bounds__(256, 2) attn_gemm2_kernel()
{
    __shared__ float As[16][132];     // +4 pad (keeps 16B align: 132*4=528=33*16)
    __shared__ float Bs[16][128];
    const int z = blockIdx.z;
    const int b = z >> 3, h = z & 7;
    const float* A    = &g_attn[(size_t)z * NN * NN];
    const float* Bm   = &g_L[h * FF];
    const float* bias = &g_V[(size_t)b * D_GAT + h * FF];
    float* C = &g_out[(size_t)b * NN * D_GAT + h * FF];

    const int tid = threadIdx.x;
    const int rowBase = blockIdx.y * 128;
    const int colBase = blockIdx.x * 128;
    const int am = tid >> 1;           // 0..127
    const int ak = (tid & 1) * 8;      // 0 or 8
    const int bk = tid >> 4;           // 0..15
    const int bn = (tid & 15) * 8;     // 0..120
    const int tx = tid & 15, ty = tid >> 4;

    unsigned long long acc[8][4];
    #pragma unroll
    for (int i = 0; i < 8; i++)
        #pragma unroll
        for (int j = 0; j < 4; j++) acc[i][j] = 0ULL;

    for (int k0 = 0; k0 < NN; k0 += 16) {
        float4 a0 = *(const float4*)&A[(size_t)(rowBase + am) * NN + k0 + ak];
        float4 a1 = *(const float4*)&A[(size_t)(rowBase + am) * NN + k0 + ak + 4];
        As[ak + 0][am] = a0.x; As[ak + 1][am] = a0.y;
        As[ak + 2][am] = a0.z; As[ak + 3][am] = a0.w;
        As[ak + 4][am] = a1.x; As[ak + 5][am] = a1.y;
        As[ak + 6][am] = a1.z; As[ak + 7][am] = a1.w;
        *(float4*)&Bs[bk][bn] =
            *(const float4*)&Bm[(size_t)(k0 + bk) * D_GAT + colBase + bn];
        *(float4*)&Bs[bk][bn + 4] =
            *(const float4*)&Bm[(size_t)(k0 + bk) * D_GAT + colBase + bn + 4];
        __syncthreads();
        #pragma unroll
        for (int kk = 0; kk < 16; kk++) {
            float4 af0 = *(const float4*)&As[kk][ty * 8];
            float4 af1 = *(const float4*)&As[kk][ty * 8 + 4];
            const unsigned long long* bp =
                (const unsigned long long*)&Bs[kk][tx * 8];
            unsigned long long b2[4];
            #pragma unroll
            for (int j = 0; j < 4; j++) b2[j] = bp[j];
            unsigned long long a2[8];
            a2[0] = pack2(af0.x); a2[1] = pack2(af0.y);
            a2[2] = pack2(af0.z); a2[3] = pack2(af0.w);
            a2[4] = pack2(af1.x); a2[5] = pack2(af1.y);
            a2[6] = pack2(af1.z); a2[7] = pack2(af1.w);
            #pragma unroll
            for (int i = 0; i < 8; i++)
                #pragma unroll
                for (int j = 0; j < 4; j++)
                    ffma2(acc[i][j], a2[i], b2[j]);
        }
        __syncthreads();
    }
    #pragma unroll
    for (int i = 0; i < 8; i++) {
        int r = rowBase + ty * 8 + i;
        float* crow = &C[(size_t)r * D_GAT + colBase + tx * 8];
        #pragma unroll
        for (int j = 0; j < 4; j++) {
            float v0, v1;
            unpack2(acc[i][j], v0, v1);
            int cc = colBase + tx * 8 + j * 2;
            v0 += bias[cc];     v1 += bias[cc + 1];
            v0 = v0 > 0.f ? v0 : expm1f(v0);
            v1 = v1 > 0.f ? v1 : expm1f(v1);
            float2 st = make_float2(v0, v1);
            *(float2*)&crow[j * 2] = st;
        }
    }
}

// ---------------- pooling logits: out . pool_q ------------------------------
__global__ void logits_kernel(const float* __restrict__ pool_q)
{
    __shared__ float sh[8];
    int bn = blockIdx.x, t = threadIdx.x;
    const float* row = &g_out[(size_t)bn * D_GAT];
    float s = 0.f;
    #pragma unroll
    for (int k = 0; k < 8; k++) {
        int d = t + k * 256;
        s += row[d] * pool_q[d];
    }
    s = warp_sum(s);
    if ((t & 31) == 0) sh[t >> 5] = s;
    __syncthreads();
    if (t == 0) {
        float S = 0.f;
        #pragma unroll
        for (int i = 0; i < 8; i++) S += sh[i];
        g_logits[bn] = S;
    }
}

// ---------------- softmax over the N label nodes ----------------------------
__global__ void pw_kernel()
{
    __shared__ float sh[8];
    __shared__ float bc;
    int b = blockIdx.x, t = threadIdx.x;
    float x = g_logits[b * NN + t];
    float m = warp_max(x);
    if ((t & 31) == 0) sh[t >> 5] = m;
    __syncthreads();
    if (t < 8) {
        float v = sh[t];
        #pragma unroll
        for (int o = 4; o; o >>= 1) v = fmaxf(v, __shfl_xor_sync(0xffu, v, o));
        if (t == 0) bc = v;
    }
    __syncthreads();
    float M = bc;
    float e = __expf(x - M);
    float s = warp_sum(e);
    if ((t & 31) == 0) sh[t >> 5] = s;
    __syncthreads();
    if (t < 8) {
        float v = sh[t];
        #pragma unroll
        for (int o = 4; o; o >>= 1) v += __shfl_xor_sync(0xffu, v, o);
        if (t == 0) bc = v;
    }
    __syncthreads();
    g_pw[b * NN + t] = e / bc;
}

// ---------------- pooled[b,d] = sum_n pw[b,n] * out[b,n,d] ------------------
__global__ void pooled_kernel()
{
    __shared__ float pw_s[NN];
    int b = blockIdx.y;
    int d = blockIdx.x * 256 + threadIdx.x;
    pw_s[threadIdx.x] = g_pw[b * NN + threadIdx.x];
    __syncthreads();
    const float* base = &g_out[(size_t)b * NN * D_GAT + d];
    float acc = 0.f;
    #pragma unroll 4
    for (int n = 0; n < NN; n++) acc += pw_s[n] * base[(size_t)n * D_GAT];
    g_pooled[b * D_GAT + d] = acc;
}

// ---------------- launch ----------------------------------------------------
extern "C" void kernel_launch(void* const* d_in, const int* in_sizes, int n_in,
                              void* d_out, int out_size)
{
    const float* visual = (const float*)d_in[0];   // (64, 2048)
    const float* labels = (const float*)d_in[1];   // (256, 512)
    const float* adj    = (const float*)d_in[2];   // (256, 256)
    const float* W      = (const float*)d_in[3];   // (2560, 8, 256)
    const float* a_src  = (const float*)d_in[4];
    const float* a_dst  = (const float*)d_in[5];
    const float* pool_q = (const float*)d_in[6];
    const float* fcW    = (const float*)d_in[7];   // (2048, 512)
    const float* fcb    = (const float*)d_in[8];
    float* out = (float*)d_out;                    // (64, 512)

    float *pL, *pV, *pVpart, *pFcpart, *pPooled;
    cudaGetSymbolAddress((void**)&pL, g_L);
    cudaGetSymbolAddress((void**)&pV, g_V);
    cudaGetSymbolAddress((void**)&pVpart, g_Vpart);
    cudaGetSymbolAddress((void**)&pFcpart, g_fcpart);
    cudaGetSymbolAddress((void**)&pPooled, g_pooled);

    // L = labels @ W[:512]   (256 x 2048, K=512)
    gemm_f32<<<dim3(D_GAT / 64, NN / 64), 256>>>(
        labels, D_LBL, W, D_GAT, pL, D_GAT, D_LBL);
    // V = visual @ W[512:]   (64 x 2048, K=2048) split-K 8
    gemm_f32_splitk<<<dim3(D_GAT / 64, 1, 8), 256>>>(
        visual, D_VIS, W + (size_t)D_LBL * D_GAT, D_GAT,
        pVpart, D_GAT, 256, (size_t)BB * D_GAT);
    reduce_parts<<<(BB * D_GAT) / 256, 256>>>(
        pVpart, pV, 8, (size_t)BB * D_GAT, BB * D_GAT, nullptr, 0);
    // attention scalars
    dots_kernel<<<NN * HH + BB * HH, 256>>>(a_src, a_dst);
    // masked softmax rows
    attn_softmax_kernel<<<(BB * HH * NN) / 8, 256>>>(adj);
    // out = ELU(attn @ L_h + V)  — packed-FFMA2 GEMM
    attn_gemm2_kernel<<<dim3(2, 2, BB * HH), 256>>>();
    // attention pooling
    logits_kernel<<<BB * NN, 256>>>(pool_q);
    pw_kernel<<<BB, 256>>>();
    pooled_kernel<<<dim3(D_GAT / 256, BB), 256>>>();
    // final fc: pooled @ fcW + b  (split-K 4)
    gemm_f32_splitk<<<dim3(D_EMB / 64, 1, 4), 256>>>(
        pPooled, D_GAT, fcW, D_EMB, pFcpart, D_EMB, 512, (size_t)BB * D_EMB);
    reduce_parts<<<(BB * D_EMB) / 256, 256>>>(
        pFcpart, out, 4, (size_t)BB * D_EMB, BB * D_EMB, fcb, D_EMB - 1);
}

// round 4
// speedup vs baseline: 1.9988x; 1.4151x over previous
#include <cuda_runtime.h>
#include <cuda_bf16.h>
#include <math.h>
#include <cstdint>

#define BB 64
#define NN 256
#define HH 8
#define FF 256
#define D_GAT 2048
#define D_LBL 512
#define D_VIS 2048
#define D_EMB 512
#define ALPHA 0.2f

// ---------------- scratch (device globals; no allocations allowed) ----------
__device__ float g_L[NN * D_GAT];                       // labels @ W_lbl (2 MiB)
__device__ __nv_bfloat16 g_LThi[HH * FF * NN];          // L^T hi plane [h][f][k]
__device__ __nv_bfloat16 g_LTlo[HH * FF * NN];          // L^T lo plane
__device__ float g_V[BB * D_GAT];
__device__ float g_Vpart[8 * BB * D_GAT];
__device__ float g_fcpart[4 * BB * D_EMB];
__device__ float g_Ls[NN * HH];
__device__ float g_Ld[NN * HH];
__device__ float g_Vs[BB * HH];
__device__ float g_Vd[BB * HH];
__device__ __nv_bfloat16 g_attn_hi[(size_t)BB * HH * NN * NN];  // 64 MiB
__device__ __nv_bfloat16 g_attn_lo[(size_t)BB * HH * NN * NN];  // 64 MiB
__device__ float g_out[(size_t)BB * NN * D_GAT];        // 128 MiB (post-ELU)
__device__ float g_logitsH[BB * NN * HH];               // per-head logit partials
__device__ float g_pw[BB * NN];
__device__ float g_pooled[BB * D_GAT];

// ---------------- helpers ---------------------------------------------------
__device__ __forceinline__ float warp_sum(float v) {
    #pragma unroll
    for (int o = 16; o; o >>= 1) v += __shfl_xor_sync(0xffffffffu, v, o);
    return v;
}
__device__ __forceinline__ float warp_max(float v) {
    #pragma unroll
    for (int o = 16; o; o >>= 1) v = fmaxf(v, __shfl_xor_sync(0xffffffffu, v, o));
    return v;
}
__device__ __forceinline__ uint32_t smem_to_u32(const void* p) {
    uint32_t a;
    asm("{ .reg .u64 t; cvta.to.shared.u64 t, %1; cvt.u32.u64 %0, t; }"
        : "=r"(a) : "l"(p));
    return a;
}
__device__ __forceinline__ void ldsm_x4(uint32_t addr, uint32_t& r0, uint32_t& r1,
                                        uint32_t& r2, uint32_t& r3) {
    asm volatile("ldmatrix.sync.aligned.m8n8.x4.shared.b16 {%0,%1,%2,%3}, [%4];"
                 : "=r"(r0), "=r"(r1), "=r"(r2), "=r"(r3) : "r"(addr));
}
__device__ __forceinline__ void mma16816(float* c, const uint32_t* a,
                                         uint32_t b0, uint32_t b1) {
    asm volatile(
        "mma.sync.aligned.m16n8k16.row.col.f32.bf16.bf16.f32 "
        "{%0,%1,%2,%3}, {%4,%5,%6,%7}, {%8,%9}, {%0,%1,%2,%3};"
        : "+f"(c[0]), "+f"(c[1]), "+f"(c[2]), "+f"(c[3])
        : "r"(a[0]), "r"(a[1]), "r"(a[2]), "r"(a[3]), "r"(b0), "r"(b1));
}

// ---------------- generic fp32 tiled GEMM: C = A(MxK) * B(KxN) --------------
__global__ void gemm_f32(const float* __restrict__ A, int lda,
                         const float* __restrict__ Bm, int ldb,
                         float* __restrict__ C, int ldc, int K)
{
    __shared__ float As[16][64];
    __shared__ float Bs[16][64];
    const int tid = threadIdx.x;
    const int tx = tid & 15, ty = tid >> 4;
    const int colBase = blockIdx.x * 64;
    const int rowBase = blockIdx.y * 64;
    const int am = tid >> 2;
    const int ak = (tid & 3) * 4;
    const int bk = tid >> 4;
    const int bn = (tid & 15) * 4;
    float acc[4][4] = {};
    for (int k0 = 0; k0 < K; k0 += 16) {
        float4 av = *(const float4*)&A[(size_t)(rowBase + am) * lda + k0 + ak];
        As[ak + 0][am] = av.x; As[ak + 1][am] = av.y;
        As[ak + 2][am] = av.z; As[ak + 3][am] = av.w;
        *(float4*)&Bs[bk][bn] =
            *(const float4*)&Bm[(size_t)(k0 + bk) * ldb + colBase + bn];
        __syncthreads();
        #pragma unroll
        for (int kk = 0; kk < 16; kk++) {
            float ra[4], rb[4];
            #pragma unroll
            for (int i = 0; i < 4; i++) ra[i] = As[kk][ty * 4 + i];
            #pragma unroll
            for (int j = 0; j < 4; j++) rb[j] = Bs[kk][tx * 4 + j];
            #pragma unroll
            for (int i = 0; i < 4; i++)
                #pragma unroll
                for (int j = 0; j < 4; j++)
                    acc[i][j] += ra[i] * rb[j];
        }
        __syncthreads();
    }
    #pragma unroll
    for (int i = 0; i < 4; i++) {
        int r = rowBase + ty * 4 + i;
        #pragma unroll
        for (int j = 0; j < 4; j++)
            C[(size_t)r * ldc + colBase + tx * 4 + j] = acc[i][j];
    }
}

__global__ void gemm_f32_splitk(const float* __restrict__ A, int lda,
                                const float* __restrict__ Bm, int ldb,
                                float* __restrict__ Cpart, int ldc,
                                int kChunk, size_t partStride)
{
    __shared__ float As[16][64];
    __shared__ float Bs[16][64];
    const int tid = threadIdx.x;
    const int tx = tid & 15, ty = tid >> 4;
    const int colBase = blockIdx.x * 64;
    const int rowBase = blockIdx.y * 64;
    const int kBase = blockIdx.z * kChunk;
    const int am = tid >> 2;
    const int ak = (tid & 3) * 4;
    const int bk = tid >> 4;
    const int bn = (tid & 15) * 4;
    float acc[4][4] = {};
    for (int k0 = kBase; k0 < kBase + kChunk; k0 += 16) {
        float4 av = *(const float4*)&A[(size_t)(rowBase + am) * lda + k0 + ak];
        As[ak + 0][am] = av.x; As[ak + 1][am] = av.y;
        As[ak + 2][am] = av.z; As[ak + 3][am] = av.w;
        *(float4*)&Bs[bk][bn] =
            *(const float4*)&Bm[(size_t)(k0 + bk) * ldb + colBase + bn];
        __syncthreads();
        #pragma unroll
        for (int kk = 0; kk < 16; kk++) {
            float ra[4], rb[4];
            #pragma unroll
            for (int i = 0; i < 4; i++) ra[i] = As[kk][ty * 4 + i];
            #pragma unroll
            for (int j = 0; j < 4; j++) rb[j] = Bs[kk][tx * 4 + j];
            #pragma unroll
            for (int i = 0; i < 4; i++)
                #pragma unroll
                for (int j = 0; j < 4; j++)
                    acc[i][j] += ra[i] * rb[j];
        }
        __syncthreads();
    }
    float* C = Cpart + blockIdx.z * partStride;
    #pragma unroll
    for (int i = 0; i < 4; i++) {
        int r = rowBase + ty * 4 + i;
        #pragma unroll
        for (int j = 0; j < 4; j++)
            C[(size_t)r * ldc + colBase + tx * 4 + j] = acc[i][j];
    }
}

__global__ void reduce_parts(const float* __restrict__ part,
                             float* __restrict__ outp,
                             int nparts, size_t stride, int total,
                             const float* __restrict__ bias, int mask)
{
    int i = blockIdx.x * 256 + threadIdx.x;
    if (i >= total) return;
    float s = 0.f;
    for (int p = 0; p < nparts; p++) s += part[p * stride + i];
    if (bias) s += bias[i & mask];
    outp[i] = s;
}

// ---------------- L^T split-bf16 planes -------------------------------------
__global__ void lt_prep_kernel()
{
    __shared__ float tile[32][33];
    const int d0 = blockIdx.x * 32;
    const int k0 = blockIdx.y * 32;
    const int tx = threadIdx.x & 31, ty = threadIdx.x >> 5;
    #pragma unroll
    for (int i = 0; i < 4; i++) {
        int k = k0 + ty + i * 8;
        tile[ty + i * 8][tx] = g_L[(size_t)k * D_GAT + d0 + tx];
    }
    __syncthreads();
    const int h = d0 >> 8;
    const int f0 = d0 & 255;
    #pragma unroll
    for (int i = 0; i < 4; i++) {
        int fl = ty + i * 8;
        float v = tile[tx][fl];
        __nv_bfloat16 hi = __float2bfloat16_rn(v);
        __nv_bfloat16 lo = __float2bfloat16_rn(v - __bfloat162float(hi));
        size_t idx = (size_t)(h * FF + f0 + fl) * NN + k0 + tx;
        g_LThi[idx] = hi;
        g_LTlo[idx] = lo;
    }
}

// ---------------- per-node / per-sample attention scalars -------------------
__global__ void dots_kernel(const float* __restrict__ a_src,
                            const float* __restrict__ a_dst)
{
    __shared__ float ss[8], sd[8];
    int idx = blockIdx.x, t = threadIdx.x;
    const float* vec; float *outS, *outD; int h;
    if (idx < NN * HH) {
        int n = idx >> 3; h = idx & 7;
        vec = &g_L[(size_t)n * D_GAT + h * FF];
        outS = &g_Ls[idx]; outD = &g_Ld[idx];
    } else {
        int k = idx - NN * HH;
        int b = k >> 3; h = k & 7;
        vec = &g_V[(size_t)b * D_GAT + h * FF];
        outS = &g_Vs[k]; outD = &g_Vd[k];
    }
    float v = vec[t];
    float s = warp_sum(v * a_src[h * FF + t]);
    float d = warp_sum(v * a_dst[h * FF + t]);
    int w = t >> 5, l = t & 31;
    if (l == 0) { ss[w] = s; sd[w] = d; }
    __syncthreads();
    if (t == 0) {
        float S = 0.f, D = 0.f;
        #pragma unroll
        for (int i = 0; i < 8; i++) { S += ss[i]; D += sd[i]; }
        *outS = S; *outD = D;
    }
}

// ---------------- masked LeakyReLU softmax rows -> bf16 hi/lo planes --------
// one warp per (b,h,i) row; 8 warps per block; all rows of a block share (b,h)
__global__ void attn_softmax_kernel(const float* __restrict__ adj)
{
    __shared__ float sLd[NN];
    int warp = threadIdx.x >> 5, lane = threadIdx.x & 31;
    int row = blockIdx.x * 8 + warp;
    int i = row & (NN - 1);
    int bh = row >> 8;
    int h = bh & 7, b = bh >> 3;
    sLd[threadIdx.x] = g_Ld[threadIdx.x * HH + h];
    __syncthreads();
    float c = g_Ls[i * HH + h] + g_Vs[b * HH + h] + g_Vd[b * HH + h];

    float4 a0 = *(const float4*)&adj[i * NN + lane * 8];
    float4 a1 = *(const float4*)&adj[i * NN + lane * 8 + 4];
    float am[8] = {a0.x, a0.y, a0.z, a0.w, a1.x, a1.y, a1.z, a1.w};

    float vals[8];
    float m = -3.4e38f;
    #pragma unroll
    for (int t = 0; t < 8; t++) {
        int j = lane * 8 + t;
        float e = c + sLd[j];
        e = e > 0.f ? e : ALPHA * e;
        vals[t] = (am[t] > 0.f) ? e : -3.4e38f;
        m = fmaxf(m, vals[t]);
    }
    m = warp_max(m);
    float s = 0.f;
    #pragma unroll
    for (int t = 0; t < 8; t++) {
        vals[t] = (vals[t] > -1e38f) ? __expf(vals[t] - m) : 0.f;
        s += vals[t];
    }
    s = warp_sum(s);
    float inv = 1.f / s;

    uint32_t hw[4], lw[4];
    #pragma unroll
    for (int t = 0; t < 4; t++) {
        float p0 = vals[t * 2] * inv;
        float p1 = vals[t * 2 + 1] * inv;
        __nv_bfloat162 hp = __floats2bfloat162_rn(p0, p1);
        float r0 = p0 - __bfloat162float(__low2bfloat16(hp));
        float r1 = p1 - __bfloat162float(__high2bfloat16(hp));
        __nv_bfloat162 lp = __floats2bfloat162_rn(r0, r1);
        hw[t] = *reinterpret_cast<uint32_t*>(&hp);
        lw[t] = *reinterpret_cast<uint32_t*>(&lp);
    }
    size_t base = (size_t)row * NN + lane * 8;
    *(uint4*)&g_attn_hi[base] = make_uint4(hw[0], hw[1], hw[2], hw[3]);
    *(uint4*)&g_attn_lo[base] = make_uint4(lw[0], lw[1], lw[2], lw[3]);
}

// ---------------- HMMA batched GEMM: out = ELU(attn @ L_h + V) --------------
// grid (2 M-halves, 512 bh); 256 thr, 8 warps (2M x 4N), warp tile 64x64
// split-bf16 3-pass; K chunks of 64 via smem; fused pooling-logit partials
#define RS 144               // padded smem row stride (bytes) = 64 bf16 + 8 pad
#define MS_A 0               // A planes: 2 x 128 rows x RS = 36864
#define MS_B 36864           // B planes: 2 x 256 rows x RS = 73728
#define MS_V 110592
#define MS_Q 111616
#define MS_LOG 112640
#define SMEM_MMA 113152

__global__ void __launch_bounds__(256, 1) attn_mma_kernel(const float* __restrict__ pool_q)
{
    extern __shared__ char sm[];
    const uint32_t smb = smem_to_u32(sm);
    const int tid = threadIdx.x;
    const int wid = tid >> 5, lane = tid & 31;
    const int wm = wid >> 2, wn = wid & 3;       // 2 x 4 warp grid
    const int mhalf = blockIdx.x;
    const int z = blockIdx.y;
    const int b = z >> 3, h = z & 7;
    const int Mbase = mhalf * 128;

    float* sV = (float*)(sm + MS_V);
    float* sQ = (float*)(sm + MS_Q);
    float* slog = (float*)(sm + MS_LOG);
    sV[tid] = g_V[b * D_GAT + h * FF + tid];
    sQ[tid] = pool_q[h * FF + tid];
    if (tid < 128) slog[tid] = 0.f;

    const __nv_bfloat16* Ahi = g_attn_hi + ((size_t)z * NN + Mbase) * NN;
    const __nv_bfloat16* Alo = g_attn_lo + ((size_t)z * NN + Mbase) * NN;
    const __nv_bfloat16* Bhi = g_LThi + (size_t)h * FF * NN;
    const __nv_bfloat16* Blo = g_LTlo + (size_t)h * FF * NN;

    float c[4][8][4];
    #pragma unroll
    for (int mt = 0; mt < 4; mt++)
        #pragma unroll
        for (int nt = 0; nt < 8; nt++)
            #pragma unroll
            for (int q = 0; q < 4; q++) c[mt][nt][q] = 0.f;

    const uint32_t rsel = lane & 15;
    const uint32_t ksel = (lane >> 4) * 16;      // byte offset of k 8-group

    for (int ck = 0; ck < 4; ck++) {
        // ---- stage A (128 rows x 64k, 2 planes) ----
        #pragma unroll
        for (int it = 0; it < 8; it++) {
            int idx = tid + it * 256;            // 0..2047
            int plane = idx >> 10, rem = idx & 1023;
            int row = rem >> 3, q = rem & 7;
            const __nv_bfloat16* src =
                (plane ? Alo : Ahi) + (size_t)row * NN + ck * 64 + q * 8;
            *(uint4*)(sm + MS_A + plane * 18432 + row * RS + q * 16) =
                *(const uint4*)src;
        }
        // ---- stage B (256 rows x 64k, 2 planes) ----
        #pragma unroll
        for (int it = 0; it < 16; it++) {
            int idx = tid + it * 256;            // 0..4095
            int plane = idx >> 11, rem = idx & 2047;
            int row = rem >> 3, q = rem & 7;
            const __nv_bfloat16* src =
                (plane ? Blo : Bhi) + (size_t)row * NN + ck * 64 + q * 8;
            *(uint4*)(sm + MS_B + plane * 36864 + row * RS + q * 16) =
                *(const uint4*)src;
        }
        __syncthreads();

        #pragma unroll
        for (int ks = 0; ks < 4; ks++) {
            uint32_t aHi[4][4], aLo[4][4], bHi[8][2], bLo[8][2];
            const uint32_t kOff = ks * 32 + ksel;
            #pragma unroll
            for (int mt = 0; mt < 4; mt++) {
                uint32_t rowo = (wm * 64 + mt * 16 + rsel) * RS + kOff;
                ldsm_x4(smb + MS_A + rowo,
                        aHi[mt][0], aHi[mt][1], aHi[mt][2], aHi[mt][3]);
                ldsm_x4(smb + MS_A + 18432 + rowo,
                        aLo[mt][0], aLo[mt][1], aLo[mt][2], aLo[mt][3]);
            }
            #pragma unroll
            for (int np = 0; np < 4; np++) {
                uint32_t rowo = (wn * 64 + np * 16 + rsel) * RS + kOff;
                uint32_t r0, r1, r2, r3;
                ldsm_x4(smb + MS_B + rowo, r0, r1, r2, r3);
                bHi[np * 2][0] = r0; bHi[np * 2][1] = r2;
                bHi[np * 2 + 1][0] = r1; bHi[np * 2 + 1][1] = r3;
                ldsm_x4(smb + MS_B + 36864 + rowo, r0, r1, r2, r3);
                bLo[np * 2][0] = r0; bLo[np * 2][1] = r2;
                bLo[np * 2 + 1][0] = r1; bLo[np * 2 + 1][1] = r3;
            }
            #pragma unroll
            for (int mt = 0; mt < 4; mt++)
                #pragma unroll
                for (int nt = 0; nt < 8; nt++) {
                    mma16816(c[mt][nt], aHi[mt], bHi[nt][0], bHi[nt][1]);
                    mma16816(c[mt][nt], aHi[mt], bLo[nt][0], bLo[nt][1]);
                    mma16816(c[mt][nt], aLo[mt], bHi[nt][0], bHi[nt][1]);
                }
        }
        __syncthreads();
    }

    // ---- epilogue: +V, ELU, store, fused pooling-logit partials ----
    #pragma unroll
    for (int mt = 0; mt < 4; mt++) {
        int rloc = wm * 64 + mt * 16 + (lane >> 2);
        float* out0 = &g_out[((size_t)(b * NN + Mbase + rloc)) * D_GAT + h * FF];
        float* out1 = out0 + 8 * D_GAT;
        float rs0 = 0.f, rs1 = 0.f;
        #pragma unroll
        for (int nt = 0; nt < 8; nt++) {
            int f = wn * 64 + nt * 8 + 2 * (lane & 3);
            float v0 = c[mt][nt][0] + sV[f];
            float v1 = c[mt][nt][1] + sV[f + 1];
            float v2 = c[mt][nt][2] + sV[f];
            float v3 = c[mt][nt][3] + sV[f + 1];
            v0 = v0 > 0.f ? v0 : expm1f(v0);
            v1 = v1 > 0.f ? v1 : expm1f(v1);
            v2 = v2 > 0.f ? v2 : expm1f(v2);
            v3 = v3 > 0.f ? v3 : expm1f(v3);
            rs0 += v0 * sQ[f] + v1 * sQ[f + 1];
            rs1 += v2 * sQ[f] + v3 * sQ[f + 1];
            *(float2*)(out0 + f) = make_float2(v0, v1);
            *(float2*)(out1 + f) = make_float2(v2, v3);
        }
        rs0 += __shfl_xor_sync(0xffffffffu, rs0, 1);
        rs0 += __shfl_xor_sync(0xffffffffu, rs0, 2);
        rs1 += __shfl_xor_sync(0xffffffffu, rs1, 1);
        rs1 += __shfl_xor_sync(0xffffffffu, rs1, 2);
        if ((lane & 3) == 0) {
            atomicAdd(&slog[rloc], rs0);
            atomicAdd(&slog[rloc + 8], rs1);
        }
    }
    __syncthreads();
    if (tid < 128)
        g_logitsH[(b * NN + Mbase + tid) * HH + h] = slog[tid];
}

// ---------------- softmax over the N label nodes (sums 8 head partials) -----
__global__ void pw_kernel()
{
    __shared__ float sh[8];
    __shared__ float bc;
    int b = blockIdx.x, t = threadIdx.x;
    const float* lp = &g_logitsH[(b * NN + t) * HH];
    float x = 0.f;
    #pragma unroll
    for (int h = 0; h < 8; h++) x += lp[h];
    float m = warp_max(x);
    if ((t & 31) == 0) sh[t >> 5] = m;
    __syncthreads();
    if (t < 8) {
        float v = sh[t];
        #pragma unroll
        for (int o = 4; o; o >>= 1) v = fmaxf(v, __shfl_xor_sync(0xffu, v, o));
        if (t == 0) bc = v;
    }
    __syncthreads();
    float M = bc;
    float e = __expf(x - M);
    float s = warp_sum(e);
    if ((t & 31) == 0) sh[t >> 5] = s;
    __syncthreads();
    if (t < 8) {
        float v = sh[t];
        #pragma unroll
        for (int o = 4; o; o >>= 1) v += __shfl_xor_sync(0xffu, v, o);
        if (t == 0) bc = v;
    }
    __syncthreads();
    g_pw[b * NN + t] = e / bc;
}

// ---------------- pooled[b,d] = sum_n pw[b,n] * out[b,n,d] ------------------
__global__ void pooled_kernel()
{
    __shared__ float pw_s[NN];
    int b = blockIdx.y;
    int d = blockIdx.x * 256 + threadIdx.x;
    pw_s[threadIdx.x] = g_pw[b * NN + threadIdx.x];
    __syncthreads();
    const float* base = &g_out[(size_t)b * NN * D_GAT + d];
    float acc = 0.f;
    #pragma unroll 4
    for (int n = 0; n < NN; n++) acc += pw_s[n] * base[(size_t)n * D_GAT];
    g_pooled[b * D_GAT + d] = acc;
}

// ---------------- launch ----------------------------------------------------
extern "C" void kernel_launch(void* const* d_in, const int* in_sizes, int n_in,
                              void* d_out, int out_size)
{
    const float* visual = (const float*)d_in[0];   // (64, 2048)
    const float* labels = (const float*)d_in[1];   // (256, 512)
    const float* adj    = (const float*)d_in[2];   // (256, 256)
    const float* W      = (const float*)d_in[3];   // (2560, 8, 256)
    const float* a_src  = (const float*)d_in[4];
    const float* a_dst  = (const float*)d_in[5];
    const float* pool_q = (const float*)d_in[6];
    const float* fcW    = (const float*)d_in[7];   // (2048, 512)
    const float* fcb    = (const float*)d_in[8];
    float* out = (float*)d_out;                    // (64, 512)

    float *pL, *pV, *pVpart, *pFcpart, *pPooled;
    cudaGetSymbolAddress((void**)&pL, g_L);
    cudaGetSymbolAddress((void**)&pV, g_V);
    cudaGetSymbolAddress((void**)&pVpart, g_Vpart);
    cudaGetSymbolAddress((void**)&pFcpart, g_fcpart);
    cudaGetSymbolAddress((void**)&pPooled, g_pooled);

    cudaFuncSetAttribute(attn_mma_kernel,
                         cudaFuncAttributeMaxDynamicSharedMemorySize, SMEM_MMA);

    // L = labels @ W[:512]   (256 x 2048, K=512)
    gemm_f32<<<dim3(D_GAT / 64, NN / 64), 256>>>(
        labels, D_LBL, W, D_GAT, pL, D_GAT, D_LBL);
    // L^T split-bf16 planes
    lt_prep_kernel<<<dim3(D_GAT / 32, NN / 32), 256>>>();
    // V = visual @ W[512:]   (64 x 2048, K=2048) split-K 8
    gemm_f32_splitk<<<dim3(D_GAT / 64, 1, 8), 256>>>(
        visual, D_VIS, W + (size_t)D_LBL * D_GAT, D_GAT,
        pVpart, D_GAT, 256, (size_t)BB * D_GAT);
    reduce_parts<<<(BB * D_GAT) / 256, 256>>>(
        pVpart, pV, 8, (size_t)BB * D_GAT, BB * D_GAT, nullptr, 0);
    // attention scalars
    dots_kernel<<<NN * HH + BB * HH, 256>>>(a_src, a_dst);
    // masked softmax rows -> bf16 hi/lo planes
    attn_softmax_kernel<<<(BB * HH * NN) / 8, 256>>>(adj);
    // out = ELU(attn @ L_h + V) via HMMA (also emits per-head logit partials)
    attn_mma_kernel<<<dim3(2, BB * HH), 256, SMEM_MMA>>>(pool_q);
    // pooling softmax + weighted sum
    pw_kernel<<<BB, 256>>>();
    pooled_kernel<<<dim3(D_GAT / 256, BB), 256>>>();
    // final fc: pooled @ fcW + b  (split-K 4)
    gemm_f32_splitk<<<dim3(D_EMB / 64, 1, 4), 256>>>(
        pPooled, D_GAT, fcW, D_EMB, pFcpart, D_EMB, 512, (size_t)BB * D_EMB);
    reduce_parts<<<(BB * D_EMB) / 256, 256>>>(
        pFcpart, out, 4, (size_t)BB * D_EMB, BB * D_EMB, fcb, D_EMB - 1);
}